// round 8
// baseline (speedup 1.0000x reference)
#include <cuda_runtime.h>
#include <cuda_fp16.h>
#include <math.h>
#include <stdint.h>

#define B_ 32
#define T_ 2048
#define D_ 1024
#define U_ 1024

// ---------------- device scratch (no allocation allowed) ----------------
__device__ float   g_cu[B_ * U_];        // query @ W2 + b2 + b1
__device__ float   g_logits[B_ * T_];    // pre-softmax scores
__device__ __half  g_w1t[U_ * D_];       // W1^T in fp16  [U, D]
__device__ float   g_cpart[8 * B_ * D_]; // context partials

// ---------------- helpers ----------------
__device__ __forceinline__ uint32_t smem_u32(const void* p) {
    uint32_t a;
    asm("{ .reg .u64 t; cvta.to.shared.u64 t, %1; cvt.u32.u64 %0, t; }" : "=r"(a) : "l"(p));
    return a;
}
__device__ __forceinline__ uint32_t pack_f16x2(float lo, float hi) {
    uint32_t r;
    asm("cvt.rn.f16x2.f32 %0, %1, %2;" : "=r"(r) : "f"(hi), "f"(lo));
    return r;
}
__device__ __forceinline__ void ldsm_x4(uint32_t& r0, uint32_t& r1, uint32_t& r2, uint32_t& r3,
                                        uint32_t addr) {
    asm volatile("ldmatrix.sync.aligned.m8n8.x4.shared.b16 {%0,%1,%2,%3}, [%4];"
                 : "=r"(r0), "=r"(r1), "=r"(r2), "=r"(r3) : "r"(addr));
}
__device__ __forceinline__ void mma16816(float* c, const uint32_t* a, uint32_t b0, uint32_t b1) {
    asm volatile(
        "mma.sync.aligned.m16n8k16.row.col.f32.f16.f16.f32 "
        "{%0,%1,%2,%3},{%4,%5,%6,%7},{%8,%9},{%0,%1,%2,%3};"
        : "+f"(c[0]), "+f"(c[1]), "+f"(c[2]), "+f"(c[3])
        : "r"(a[0]), "r"(a[1]), "r"(a[2]), "r"(a[3]), "r"(b0), "r"(b1));
}
__device__ __forceinline__ void cp_async16(uint32_t sdst, const void* gsrc) {
    asm volatile("cp.async.cg.shared.global [%0], [%1], 16;" :: "r"(sdst), "l"(gsrc));
}
__device__ __forceinline__ void cp_commit() {
    asm volatile("cp.async.commit_group;" ::: "memory");
}
__device__ __forceinline__ void cp_wait1() {
    asm volatile("cp.async.wait_group 1;" ::: "memory");
}

// ---------------------------------------------------------------------------
// W1 [D,U] fp32 -> g_w1t [U,D] fp16 (transpose + convert)
// ---------------------------------------------------------------------------
__global__ void w1t_kernel(const float* __restrict__ W1)
{
    __shared__ float tile[32][33];
    const int u0 = blockIdx.x * 32, d0 = blockIdx.y * 32;
    const int tx = threadIdx.x, ty = threadIdx.y;
#pragma unroll
    for (int i = 0; i < 32; i += 8)
        tile[ty + i][tx] = W1[(size_t)(d0 + ty + i) * U_ + u0 + tx];
    __syncthreads();
#pragma unroll
    for (int i = 0; i < 32; i += 8)
        g_w1t[(size_t)(u0 + ty + i) * D_ + d0 + tx] = __float2half_rn(tile[tx][ty + i]);
}

// ---------------------------------------------------------------------------
// q_proj (+ b2 + b1 fused)
// ---------------------------------------------------------------------------
__global__ void qproj_kernel(const float* __restrict__ query,
                             const float* __restrict__ W2,
                             const float* __restrict__ b2,
                             const float* __restrict__ b1)
{
    __shared__ float qs[D_];
    const int b = blockIdx.y;
    const int u = blockIdx.x * blockDim.x + threadIdx.x;
    for (int d = threadIdx.x; d < D_; d += blockDim.x)
        qs[d] = query[b * D_ + d];
    __syncthreads();
    float acc = b2[u] + b1[u];
#pragma unroll 8
    for (int d = 0; d < D_; ++d)
        acc = fmaf(qs[d], W2[(size_t)d * U_ + u], acc);
    g_cu[b * U_ + u] = acc;
}

// ---------------------------------------------------------------------------
// Fused score GEMM (mma.sync fp16), 512 threads (16 warps), 3-stage ring:
//   logits[b,t] = V . tanh(values[b,t,:] @ W1 + qproj_cu[b,:]) + bv
// CTA: 64 t-rows; A (64x1024 fp16) resident. 4 passes over U (256 u each);
// B streamed in 64 chunks of 256u x 64k (32KB), 3 stages, 2 in flight,
// one __syncthreads per chunk. Warp grid 2(m) x 8(n): each warp 32t x 32u.
// 4 warps/SMSP hide LDSM + mma dependency latency.
// ---------------------------------------------------------------------------
#define NCHUNK 64                      // 4 passes x 16 chunks
#define SMA    0                       // 64 x 2048B = 131072
#define SMB    131072                  // 3 stages x 32768
#define SMRED  (SMB + 3 * 32768)       // 64 x 8 f32
#define SMTOT  (SMRED + 2048)          // 231424 bytes

__global__ void __launch_bounds__(512, 1)
score_kernel(const float* __restrict__ values,
             const float* __restrict__ V,
             const float* __restrict__ bv)
{
    extern __shared__ char smem[];
    const uint32_t sb = smem_u32(smem);
    const int tid  = threadIdx.x;
    const int lane = tid & 31;
    const int warp = tid >> 5;
    const int warp_m = warp & 1;     // 2 x 32 rows
    const int warp_n = warp >> 1;    // 8 x 32 cols
    const int g8 = lane >> 2;
    const int t4 = lane & 3;

    const int b  = blockIdx.x >> 5;          // 32 t-tiles per batch
    const int t0 = (blockIdx.x & 31) * 64;

    float* sred = (float*)(smem + SMRED);

    // chunk issue: 256u x 64k fp16 into stage gc%3; 128B rows, xor-swizzled
    auto issue_chunk = [&](int gc) {
        if (gc < NCHUNK) {
            const int p = gc >> 4, c = gc & 15;
            const __half* src0 = g_w1t + (size_t)(p * 256) * D_ + c * 64;
            uint32_t dbase = sb + SMB + (gc % 3) * 32768;
#pragma unroll
            for (int j = 0; j < 4; ++j) {
                int idx = tid + j * 512;       // 2048 slots of 16B
                int row = idx >> 3, cs = idx & 7;
                cp_async16(dbase + row * 128 + ((cs ^ (row & 7)) << 4),
                           src0 + (size_t)row * D_ + cs * 8);
            }
        }
        cp_commit();
    };

    // ---- A resident: 64 rows x 1024 k, fp32 -> fp16, xor-swizzled ----
    const float* vbase = values + ((size_t)b * T_ + t0) * D_;
#pragma unroll 4
    for (int it = 0; it < 16; ++it) {
        int idx = tid + it * 512;             // 8192 slots of 8 fp16
        int row = idx >> 7;
        int c   = idx & 127;
        const float* src = vbase + (size_t)row * D_ + c * 8;
        float4 f0 = *(const float4*)(src);
        float4 f1 = *(const float4*)(src + 4);
        uint4 o;
        o.x = pack_f16x2(f0.x, f0.y);
        o.y = pack_f16x2(f0.z, f0.w);
        o.z = pack_f16x2(f1.x, f1.y);
        o.w = pack_f16x2(f1.z, f1.w);
        *(uint4*)(smem + SMA + row * 2048 + ((c ^ (row & 7)) << 4)) = o;
    }

    // prologue: 2 chunks in flight
    issue_chunk(0);
    issue_chunk(1);

    float spart[4] = {0.f, 0.f, 0.f, 0.f};
    int g = 0;

    for (int pass = 0; pass < 4; ++pass) {
        const int u0 = pass * 256;

        float acc[2][4][4];        // [mt][j = nt*2+half][frag]
#pragma unroll
        for (int mt = 0; mt < 2; ++mt)
#pragma unroll
            for (int j = 0; j < 4; ++j)
#pragma unroll
                for (int r = 0; r < 4; ++r) acc[mt][j][r] = 0.f;

        for (int c = 0; c < 16; ++c, ++g) {
            cp_wait1();          // chunk g landed
            __syncthreads();     // all warps done reading stage (g-1)%3
            issue_chunk(g + 2);  // refill freed stage under this chunk's HMMAs

            const uint32_t bbase = sb + SMB + (g % 3) * 32768;
#pragma unroll
            for (int ks = 0; ks < 4; ++ks) {
                const int kk = c * 4 + ks;     // k/16 index within pass
                uint32_t a[2][4];
#pragma unroll
                for (int mt = 0; mt < 2; ++mt) {
                    int row = warp_m * 32 + mt * 16 + (lane & 15);
                    int cc  = kk * 2 + (lane >> 4);
                    uint32_t addr = sb + SMA + row * 2048 + ((cc ^ (row & 7)) << 4);
                    ldsm_x4(a[mt][0], a[mt][1], a[mt][2], a[mt][3], addr);
                }
#pragma unroll
                for (int nt = 0; nt < 2; ++nt) {
                    int row = warp_n * 32 + nt * 16 + (lane & 15);
                    int ss  = ks * 2 + (lane >> 4);
                    uint32_t addr = bbase + row * 128 + ((ss ^ (row & 7)) << 4);
                    uint32_t r0, r1, r2, r3;
                    ldsm_x4(r0, r1, r2, r3, addr);
#pragma unroll
                    for (int mt = 0; mt < 2; ++mt) {
                        mma16816(acc[mt][nt * 2 + 0], a[mt], r0, r2);  // cols +0..7
                        mma16816(acc[mt][nt * 2 + 1], a[mt], r1, r3);  // cols +8..15
                    }
                }
            }
        }

        // ---- epilogue: tanh + dot V folded into per-row partials ----
        float cuv[8], vvv[8];
#pragma unroll
        for (int j = 0; j < 4; ++j)
#pragma unroll
            for (int e = 0; e < 2; ++e) {
                int u = u0 + warp_n * 32 + j * 8 + t4 * 2 + e;
                cuv[j * 2 + e] = g_cu[b * U_ + u];
                vvv[j * 2 + e] = V[u];
            }
#pragma unroll
        for (int mt = 0; mt < 2; ++mt)
#pragma unroll
            for (int j = 0; j < 4; ++j)
#pragma unroll
                for (int r = 0; r < 4; ++r) {
                    float x = acc[mt][j][r] + cuv[j * 2 + (r & 1)];
                    spart[mt * 2 + (r >> 1)] =
                        fmaf(tanhf(x), vvv[j * 2 + (r & 1)], spart[mt * 2 + (r >> 1)]);
                }
    }

    // reduce across quad lanes (cols), stash per-warp_n partials
#pragma unroll
    for (int s = 0; s < 4; ++s) {
        float v = spart[s];
        v += __shfl_xor_sync(0xffffffffu, v, 1);
        v += __shfl_xor_sync(0xffffffffu, v, 2);
        if (t4 == 0) {
            int row = warp_m * 32 + (s >> 1) * 16 + (s & 1) * 8 + g8;
            sred[row * 8 + warp_n] = v;
        }
    }
    __syncthreads();
    if (tid < 64) {
        const float* rp = &sred[tid * 8];
        float s = ((rp[0] + rp[1]) + (rp[2] + rp[3]))
                + ((rp[4] + rp[5]) + (rp[6] + rp[7]));
        g_logits[b * T_ + t0 + tid] = s + bv[0];
    }
}

// ---------------------------------------------------------------------------
// softmax over T per batch
// ---------------------------------------------------------------------------
__global__ void softmax_kernel(float* __restrict__ weights)
{
    __shared__ float red[256];
    const int b = blockIdx.x;
    const int tid = threadIdx.x;

    float m = -INFINITY;
    for (int t = tid; t < T_; t += 256)
        m = fmaxf(m, g_logits[b * T_ + t]);
    red[tid] = m;
    __syncthreads();
    for (int s = 128; s > 0; s >>= 1) {
        if (tid < s) red[tid] = fmaxf(red[tid], red[tid + s]);
        __syncthreads();
    }
    m = red[0];
    __syncthreads();

    float sum = 0.0f;
    for (int t = tid; t < T_; t += 256)
        sum += expf(g_logits[b * T_ + t] - m);
    red[tid] = sum;
    __syncthreads();
    for (int s = 128; s > 0; s >>= 1) {
        if (tid < s) red[tid] += red[tid + s];
        __syncthreads();
    }
    const float inv = 1.0f / red[0];

    for (int t = tid; t < T_; t += 256)
        weights[b * T_ + t] = expf(g_logits[b * T_ + t] - m) * inv;
}

// ---------------------------------------------------------------------------
// context: two-stage deterministic reduction over T
// ---------------------------------------------------------------------------
__global__ void context_part_kernel(const float* __restrict__ values,
                                    const float* __restrict__ weights)
{
    __shared__ float w[256];
    const int b = blockIdx.y;
    const int chunk = blockIdx.z;
    const int d = blockIdx.x * 128 + threadIdx.x;
    const int tbase = chunk * 256;

    for (int t = threadIdx.x; t < 256; t += 128)
        w[t] = weights[b * T_ + tbase + t];
    __syncthreads();

    const float* vp = values + ((size_t)b * T_ + tbase) * D_ + d;
    float a0 = 0.f, a1 = 0.f, a2 = 0.f, a3 = 0.f;
#pragma unroll 4
    for (int t = 0; t < 256; t += 4) {
        a0 = fmaf(w[t + 0], vp[(size_t)(t + 0) * D_], a0);
        a1 = fmaf(w[t + 1], vp[(size_t)(t + 1) * D_], a1);
        a2 = fmaf(w[t + 2], vp[(size_t)(t + 2) * D_], a2);
        a3 = fmaf(w[t + 3], vp[(size_t)(t + 3) * D_], a3);
    }
    g_cpart[(chunk * B_ + b) * D_ + d] = (a0 + a1) + (a2 + a3);
}

__global__ void context_reduce_kernel(float* __restrict__ context)
{
    const int i = blockIdx.x * 256 + threadIdx.x;   // over B*D
    float s = 0.0f;
#pragma unroll
    for (int c = 0; c < 8; ++c)
        s += g_cpart[c * (B_ * D_) + i];
    context[i] = s;
}

// ---------------------------------------------------------------------------
extern "C" void kernel_launch(void* const* d_in, const int* in_sizes, int n_in,
                              void* d_out, int out_size)
{
    const float* query  = (const float*)d_in[0];
    const float* values = (const float*)d_in[1];
    const float* W1     = (const float*)d_in[2];
    const float* b1     = (const float*)d_in[3];
    const float* W2     = (const float*)d_in[4];
    const float* b2     = (const float*)d_in[5];
    const float* V      = (const float*)d_in[6];
    const float* bv     = (const float*)d_in[7];

    float* out     = (float*)d_out;
    float* context = out;             // [B, D]
    float* weights = out + B_ * D_;   // [B, T, 1]

    cudaFuncSetAttribute(score_kernel,
                         cudaFuncAttributeMaxDynamicSharedMemorySize, SMTOT);

    w1t_kernel<<<dim3(U_ / 32, D_ / 32), dim3(32, 8)>>>(W1);
    qproj_kernel<<<dim3(U_ / 256, B_), 256>>>(query, W2, b2, b1);
    score_kernel<<<(B_ * T_) / 64, 512, SMTOT>>>(values, V, bv);
    softmax_kernel<<<B_, 256>>>(weights);
    context_part_kernel<<<dim3(D_ / 128, B_, 8), 128>>>(values, weights);
    context_reduce_kernel<<<(B_ * D_) / 256, 256>>>(context);
}

// round 9
// speedup vs baseline: 1.1363x; 1.1363x over previous
#include <cuda_runtime.h>
#include <cuda_fp16.h>
#include <math.h>
#include <stdint.h>

#define B_ 32
#define T_ 2048
#define D_ 1024
#define U_ 1024

// ---------------- device scratch (no allocation allowed) ----------------
__device__ float   g_cu[B_ * U_];         // query @ W2 + b2 + b1
__device__ float   g_qpart[8 * B_ * U_];  // qproj split-K partials
__device__ float   g_logits[B_ * T_];     // pre-softmax scores
__device__ __half  g_w1t[U_ * D_];        // W1^T in fp16  [U, D]
__device__ float   g_cpart[16 * B_ * D_]; // context partials

// ---------------- helpers ----------------
__device__ __forceinline__ uint32_t smem_u32(const void* p) {
    uint32_t a;
    asm("{ .reg .u64 t; cvta.to.shared.u64 t, %1; cvt.u32.u64 %0, t; }" : "=r"(a) : "l"(p));
    return a;
}
__device__ __forceinline__ uint32_t pack_f16x2(float lo, float hi) {
    uint32_t r;
    asm("cvt.rn.f16x2.f32 %0, %1, %2;" : "=r"(r) : "f"(hi), "f"(lo));
    return r;
}
__device__ __forceinline__ void ldsm_x4(uint32_t& r0, uint32_t& r1, uint32_t& r2, uint32_t& r3,
                                        uint32_t addr) {
    asm volatile("ldmatrix.sync.aligned.m8n8.x4.shared.b16 {%0,%1,%2,%3}, [%4];"
                 : "=r"(r0), "=r"(r1), "=r"(r2), "=r"(r3) : "r"(addr));
}
__device__ __forceinline__ void mma16816(float* c, const uint32_t* a, uint32_t b0, uint32_t b1) {
    asm volatile(
        "mma.sync.aligned.m16n8k16.row.col.f32.f16.f16.f32 "
        "{%0,%1,%2,%3},{%4,%5,%6,%7},{%8,%9},{%0,%1,%2,%3};"
        : "+f"(c[0]), "+f"(c[1]), "+f"(c[2]), "+f"(c[3])
        : "r"(a[0]), "r"(a[1]), "r"(a[2]), "r"(a[3]), "r"(b0), "r"(b1));
}
__device__ __forceinline__ void cp_async16(uint32_t sdst, const void* gsrc) {
    asm volatile("cp.async.cg.shared.global [%0], [%1], 16;" :: "r"(sdst), "l"(gsrc));
}
__device__ __forceinline__ void cp_commit() {
    asm volatile("cp.async.commit_group;" ::: "memory");
}
__device__ __forceinline__ void cp_wait1() {
    asm volatile("cp.async.wait_group 1;" ::: "memory");
}

// ---------------------------------------------------------------------------
// W1 [D,U] fp32 -> g_w1t [U,D] fp16 (transpose + convert)
// ---------------------------------------------------------------------------
__global__ void w1t_kernel(const float* __restrict__ W1)
{
    __shared__ float tile[32][33];
    const int u0 = blockIdx.x * 32, d0 = blockIdx.y * 32;
    const int tx = threadIdx.x, ty = threadIdx.y;
#pragma unroll
    for (int i = 0; i < 32; i += 8)
        tile[ty + i][tx] = W1[(size_t)(d0 + ty + i) * U_ + u0 + tx];
    __syncthreads();
#pragma unroll
    for (int i = 0; i < 32; i += 8)
        g_w1t[(size_t)(u0 + ty + i) * D_ + d0 + tx] = __float2half_rn(tile[tx][ty + i]);
}

// ---------------------------------------------------------------------------
// q_proj split-K: partial dot over 128 d's per block
// grid (U/256, B, 8), block 256
// ---------------------------------------------------------------------------
__global__ void qproj_part_kernel(const float* __restrict__ query,
                                  const float* __restrict__ W2)
{
    __shared__ float qs[128];
    const int b = blockIdx.y;
    const int c = blockIdx.z;
    const int u = blockIdx.x * 256 + threadIdx.x;
    const int d0 = c * 128;

    if (threadIdx.x < 128)
        qs[threadIdx.x] = query[b * D_ + d0 + threadIdx.x];
    __syncthreads();

    float acc = 0.0f;
#pragma unroll 8
    for (int i = 0; i < 128; ++i)
        acc = fmaf(qs[i], W2[(size_t)(d0 + i) * U_ + u], acc);
    g_qpart[(c * B_ + b) * U_ + u] = acc;
}

__global__ void qproj_reduce_kernel(const float* __restrict__ b1,
                                    const float* __restrict__ b2)
{
    const int i = blockIdx.x * 256 + threadIdx.x;   // over B*U
    const int u = i & (U_ - 1);
    float s = b1[u] + b2[u];
#pragma unroll
    for (int c = 0; c < 8; ++c)
        s += g_qpart[c * (B_ * U_) + i];
    g_cu[i] = s;
}

// ---------------------------------------------------------------------------
// Fused score GEMM (mma.sync fp16), 3-stage cp.async ring, 1 sync per chunk.
// At the legacy-HMMA roofline (~16 cyc/mma/SMSP); B prologue hoisted ahead
// of the A-load so the first chunks' L2 latency hides under A conversion.
// ---------------------------------------------------------------------------
#define NCHUNK 64                      // 4 passes x 16 chunks
#define SMA    0                       // 64 x 2048B = 131072
#define SMB    131072                  // 3 stages x 32768
#define SMRED  (SMB + 3 * 32768)       // 64 x 4 f32
#define SMTOT  (SMRED + 1024)          // 230400 bytes

__global__ void __launch_bounds__(256, 1)
score_kernel(const float* __restrict__ values,
             const float* __restrict__ V,
             const float* __restrict__ bv)
{
    extern __shared__ char smem[];
    const uint32_t sb = smem_u32(smem);
    const int tid  = threadIdx.x;
    const int lane = tid & 31;
    const int warp = tid >> 5;
    const int warp_m = warp & 1;
    const int warp_n = warp >> 1;
    const int g8 = lane >> 2;
    const int t4 = lane & 3;

    const int b  = blockIdx.x >> 5;          // 32 t-tiles per batch
    const int t0 = (blockIdx.x & 31) * 64;

    float* sred = (float*)(smem + SMRED);

    // chunk issue: 256u x 64k fp16 into stage gc%3; 128B rows, xor-swizzled
    auto issue_chunk = [&](int gc) {
        if (gc < NCHUNK) {
            const int p = gc >> 4, c = gc & 15;
            const __half* src0 = g_w1t + (size_t)(p * 256) * D_ + c * 64;
            uint32_t dbase = sb + SMB + (gc % 3) * 32768;
#pragma unroll
            for (int j = 0; j < 8; ++j) {
                int idx = tid + j * 256;       // 2048 slots of 16B
                int row = idx >> 3, cs = idx & 7;
                cp_async16(dbase + row * 128 + ((cs ^ (row & 7)) << 4),
                           src0 + (size_t)row * D_ + cs * 8);
            }
        }
        cp_commit();   // always commit to keep wait_group counting exact
    };

    // prologue FIRST: 2 chunks in flight while we load/convert A
    issue_chunk(0);
    issue_chunk(1);

    // ---- A resident: 64 rows x 1024 k, fp32 -> fp16, xor-swizzled ----
    const float* vbase = values + ((size_t)b * T_ + t0) * D_;
#pragma unroll 4
    for (int it = 0; it < 32; ++it) {
        int idx = tid + it * 256;             // 8192 slots of 8 fp16
        int row = idx >> 7;
        int c   = idx & 127;
        const float* src = vbase + (size_t)row * D_ + c * 8;
        float4 f0 = *(const float4*)(src);
        float4 f1 = *(const float4*)(src + 4);
        uint4 o;
        o.x = pack_f16x2(f0.x, f0.y);
        o.y = pack_f16x2(f0.z, f0.w);
        o.z = pack_f16x2(f1.x, f1.y);
        o.w = pack_f16x2(f1.z, f1.w);
        *(uint4*)(smem + SMA + row * 2048 + ((c ^ (row & 7)) << 4)) = o;
    }

    float spart[4] = {0.f, 0.f, 0.f, 0.f};
    int g = 0;

    for (int pass = 0; pass < 4; ++pass) {
        const int u0 = pass * 256;

        float acc[2][8][4];
#pragma unroll
        for (int mt = 0; mt < 2; ++mt)
#pragma unroll
            for (int j = 0; j < 8; ++j)
#pragma unroll
                for (int r = 0; r < 4; ++r) acc[mt][j][r] = 0.f;

        for (int c = 0; c < 16; ++c, ++g) {
            cp_wait1();          // chunk g landed
            __syncthreads();     // A visible (1st iter); stage (g-1)%3 free
            issue_chunk(g + 2);  // refill freed stage under this chunk's HMMAs

            const uint32_t bbase = sb + SMB + (g % 3) * 32768;
#pragma unroll
            for (int ks = 0; ks < 4; ++ks) {
                const int kk = c * 4 + ks;
                uint32_t a[2][4];
#pragma unroll
                for (int mt = 0; mt < 2; ++mt) {
                    int row = warp_m * 32 + mt * 16 + (lane & 15);
                    int cc  = kk * 2 + (lane >> 4);
                    uint32_t addr = sb + SMA + row * 2048 + ((cc ^ (row & 7)) << 4);
                    ldsm_x4(a[mt][0], a[mt][1], a[mt][2], a[mt][3], addr);
                }
#pragma unroll
                for (int nt = 0; nt < 4; ++nt) {
                    int row = warp_n * 64 + nt * 16 + (lane & 15);
                    int ss  = ks * 2 + (lane >> 4);
                    uint32_t addr = bbase + row * 128 + ((ss ^ (row & 7)) << 4);
                    uint32_t r0, r1, r2, r3;
                    ldsm_x4(r0, r1, r2, r3, addr);
#pragma unroll
                    for (int mt = 0; mt < 2; ++mt) {
                        mma16816(acc[mt][nt * 2 + 0], a[mt], r0, r2);  // cols +0..7
                        mma16816(acc[mt][nt * 2 + 1], a[mt], r1, r3);  // cols +8..15
                    }
                }
            }
        }

        // ---- epilogue: tanh + dot V folded into per-row partials ----
        float cuv[16], vvv[16];
#pragma unroll
        for (int j = 0; j < 8; ++j)
#pragma unroll
            for (int e = 0; e < 2; ++e) {
                int u = u0 + warp_n * 64 + j * 8 + t4 * 2 + e;
                cuv[j * 2 + e] = g_cu[b * U_ + u];
                vvv[j * 2 + e] = V[u];
            }
#pragma unroll
        for (int mt = 0; mt < 2; ++mt)
#pragma unroll
            for (int j = 0; j < 8; ++j)
#pragma unroll
                for (int r = 0; r < 4; ++r) {
                    float x = acc[mt][j][r] + cuv[j * 2 + (r & 1)];
                    spart[mt * 2 + (r >> 1)] =
                        fmaf(tanhf(x), vvv[j * 2 + (r & 1)], spart[mt * 2 + (r >> 1)]);
                }
    }

    // reduce across quad lanes (cols), stash per-warp_n partials
#pragma unroll
    for (int s = 0; s < 4; ++s) {
        float v = spart[s];
        v += __shfl_xor_sync(0xffffffffu, v, 1);
        v += __shfl_xor_sync(0xffffffffu, v, 2);
        if (t4 == 0) {
            int row = warp_m * 32 + (s >> 1) * 16 + (s & 1) * 8 + g8;
            sred[row * 4 + warp_n] = v;
        }
    }
    __syncthreads();
    if (tid < 64) {
        const float* rp = &sred[tid * 4];
        g_logits[b * T_ + t0 + tid] = (rp[0] + rp[1]) + (rp[2] + rp[3]) + bv[0];
    }
}

// ---------------------------------------------------------------------------
// softmax over T per batch
// ---------------------------------------------------------------------------
__global__ void softmax_kernel(float* __restrict__ weights)
{
    __shared__ float red[256];
    const int b = blockIdx.x;
    const int tid = threadIdx.x;

    float m = -INFINITY;
    for (int t = tid; t < T_; t += 256)
        m = fmaxf(m, g_logits[b * T_ + t]);
    red[tid] = m;
    __syncthreads();
    for (int s = 128; s > 0; s >>= 1) {
        if (tid < s) red[tid] = fmaxf(red[tid], red[tid + s]);
        __syncthreads();
    }
    m = red[0];
    __syncthreads();

    float sum = 0.0f;
    for (int t = tid; t < T_; t += 256)
        sum += expf(g_logits[b * T_ + t] - m);
    red[tid] = sum;
    __syncthreads();
    for (int s = 128; s > 0; s >>= 1) {
        if (tid < s) red[tid] += red[tid + s];
        __syncthreads();
    }
    const float inv = 1.0f / red[0];

    for (int t = tid; t < T_; t += 256)
        weights[b * T_ + t] = expf(g_logits[b * T_ + t] - m) * inv;
}

// ---------------------------------------------------------------------------
// context: two-stage deterministic reduction over T, float4 loads
// stage 1: grid (D/256, B, 16), block 64 — each block reduces 128 t's
// ---------------------------------------------------------------------------
__global__ void context_part_kernel(const float* __restrict__ values,
                                    const float* __restrict__ weights)
{
    __shared__ float w[128];
    const int b = blockIdx.y;
    const int chunk = blockIdx.z;
    const int d4 = blockIdx.x * 64 + threadIdx.x;   // float4 index
    const int tbase = chunk * 128;

    for (int t = threadIdx.x; t < 128; t += 64)
        w[t] = weights[b * T_ + tbase + t];
    __syncthreads();

    const float4* vp4 = (const float4*)(values + ((size_t)b * T_ + tbase) * D_) + d4;
    float4 a0 = {0,0,0,0}, a1 = {0,0,0,0}, a2 = {0,0,0,0}, a3 = {0,0,0,0};
#pragma unroll 2
    for (int t = 0; t < 128; t += 4) {
        float4 f0 = vp4[(size_t)(t + 0) * (D_ / 4)];
        float4 f1 = vp4[(size_t)(t + 1) * (D_ / 4)];
        float4 f2 = vp4[(size_t)(t + 2) * (D_ / 4)];
        float4 f3 = vp4[(size_t)(t + 3) * (D_ / 4)];
        float w0 = w[t], w1 = w[t + 1], w2 = w[t + 2], w3 = w[t + 3];
        a0.x = fmaf(w0, f0.x, a0.x); a0.y = fmaf(w0, f0.y, a0.y);
        a0.z = fmaf(w0, f0.z, a0.z); a0.w = fmaf(w0, f0.w, a0.w);
        a1.x = fmaf(w1, f1.x, a1.x); a1.y = fmaf(w1, f1.y, a1.y);
        a1.z = fmaf(w1, f1.z, a1.z); a1.w = fmaf(w1, f1.w, a1.w);
        a2.x = fmaf(w2, f2.x, a2.x); a2.y = fmaf(w2, f2.y, a2.y);
        a2.z = fmaf(w2, f2.z, a2.z); a2.w = fmaf(w2, f2.w, a2.w);
        a3.x = fmaf(w3, f3.x, a3.x); a3.y = fmaf(w3, f3.y, a3.y);
        a3.z = fmaf(w3, f3.z, a3.z); a3.w = fmaf(w3, f3.w, a3.w);
    }
    float4 r;
    r.x = (a0.x + a1.x) + (a2.x + a3.x);
    r.y = (a0.y + a1.y) + (a2.y + a3.y);
    r.z = (a0.z + a1.z) + (a2.z + a3.z);
    r.w = (a0.w + a1.w) + (a2.w + a3.w);
    ((float4*)(g_cpart + (size_t)(chunk * B_ + b) * D_))[d4] = r;
}

__global__ void context_reduce_kernel(float* __restrict__ context)
{
    const int i = blockIdx.x * 256 + threadIdx.x;   // over B*D
    float s = 0.0f;
#pragma unroll
    for (int c = 0; c < 16; ++c)
        s += g_cpart[c * (B_ * D_) + i];
    context[i] = s;
}

// ---------------------------------------------------------------------------
extern "C" void kernel_launch(void* const* d_in, const int* in_sizes, int n_in,
                              void* d_out, int out_size)
{
    const float* query  = (const float*)d_in[0];
    const float* values = (const float*)d_in[1];
    const float* W1     = (const float*)d_in[2];
    const float* b1     = (const float*)d_in[3];
    const float* W2     = (const float*)d_in[4];
    const float* b2     = (const float*)d_in[5];
    const float* V      = (const float*)d_in[6];
    const float* bv     = (const float*)d_in[7];

    float* out     = (float*)d_out;
    float* context = out;             // [B, D]
    float* weights = out + B_ * D_;   // [B, T, 1]

    cudaFuncSetAttribute(score_kernel,
                         cudaFuncAttributeMaxDynamicSharedMemorySize, SMTOT);

    w1t_kernel<<<dim3(U_ / 32, D_ / 32), dim3(32, 8)>>>(W1);
    qproj_part_kernel<<<dim3(U_ / 256, B_, 8), 256>>>(query, W2);
    qproj_reduce_kernel<<<(B_ * U_) / 256, 256>>>(b1, b2);
    score_kernel<<<(B_ * T_) / 64, 256, SMTOT>>>(values, V, bv);
    softmax_kernel<<<B_, 256>>>(weights);
    context_part_kernel<<<dim3(D_ / 256, B_, 16), 64>>>(values, weights);
    context_reduce_kernel<<<(B_ * D_) / 256, 256>>>(context);
}

// round 10
// speedup vs baseline: 1.1532x; 1.0149x over previous
#include <cuda_runtime.h>
#include <cuda_fp16.h>
#include <math.h>
#include <stdint.h>

#define B_ 32
#define T_ 2048
#define D_ 1024
#define U_ 1024

// ---------------- device scratch (no allocation allowed) ----------------
__device__ float   g_cu[B_ * U_];         // query @ W2 + b2 + b1
__device__ float   g_qpart[8 * B_ * U_];  // qproj split-K partials
__device__ float   g_logits[B_ * T_];     // pre-softmax scores
__device__ __half  g_w1t[U_ * D_];        // W1^T in fp16  [U, D]
__device__ float   g_cpart[16 * B_ * D_]; // context partials

// ---------------- helpers ----------------
__device__ __forceinline__ uint32_t smem_u32(const void* p) {
    uint32_t a;
    asm("{ .reg .u64 t; cvta.to.shared.u64 t, %1; cvt.u32.u64 %0, t; }" : "=r"(a) : "l"(p));
    return a;
}
__device__ __forceinline__ uint32_t pack_f16x2(float lo, float hi) {
    uint32_t r;
    asm("cvt.rn.f16x2.f32 %0, %1, %2;" : "=r"(r) : "f"(hi), "f"(lo));
    return r;
}
__device__ __forceinline__ void ldsm_x4(uint32_t& r0, uint32_t& r1, uint32_t& r2, uint32_t& r3,
                                        uint32_t addr) {
    asm volatile("ldmatrix.sync.aligned.m8n8.x4.shared.b16 {%0,%1,%2,%3}, [%4];"
                 : "=r"(r0), "=r"(r1), "=r"(r2), "=r"(r3) : "r"(addr));
}
__device__ __forceinline__ void mma16816(float* c, const uint32_t* a, uint32_t b0, uint32_t b1) {
    asm volatile(
        "mma.sync.aligned.m16n8k16.row.col.f32.f16.f16.f32 "
        "{%0,%1,%2,%3},{%4,%5,%6,%7},{%8,%9},{%0,%1,%2,%3};"
        : "+f"(c[0]), "+f"(c[1]), "+f"(c[2]), "+f"(c[3])
        : "r"(a[0]), "r"(a[1]), "r"(a[2]), "r"(a[3]), "r"(b0), "r"(b1));
}
__device__ __forceinline__ void cp_async16(uint32_t sdst, const void* gsrc) {
    asm volatile("cp.async.cg.shared.global [%0], [%1], 16;" :: "r"(sdst), "l"(gsrc));
}
__device__ __forceinline__ void cp_commit() {
    asm volatile("cp.async.commit_group;" ::: "memory");
}
__device__ __forceinline__ void cp_wait1() {
    asm volatile("cp.async.wait_group 1;" ::: "memory");
}

// ---------------------------------------------------------------------------
// W1 [D,U] fp32 -> g_w1t [U,D] fp16 (transpose + convert)
// ---------------------------------------------------------------------------
__global__ void w1t_kernel(const float* __restrict__ W1)
{
    __shared__ float tile[32][33];
    const int u0 = blockIdx.x * 32, d0 = blockIdx.y * 32;
    const int tx = threadIdx.x, ty = threadIdx.y;
#pragma unroll
    for (int i = 0; i < 32; i += 8)
        tile[ty + i][tx] = W1[(size_t)(d0 + ty + i) * U_ + u0 + tx];
    __syncthreads();
#pragma unroll
    for (int i = 0; i < 32; i += 8)
        g_w1t[(size_t)(u0 + ty + i) * D_ + d0 + tx] = __float2half_rn(tile[tx][ty + i]);
}

// ---------------------------------------------------------------------------
// q_proj split-K: partial dot over 128 d's per block
// ---------------------------------------------------------------------------
__global__ void qproj_part_kernel(const float* __restrict__ query,
                                  const float* __restrict__ W2)
{
    __shared__ float qs[128];
    const int b = blockIdx.y;
    const int c = blockIdx.z;
    const int u = blockIdx.x * 256 + threadIdx.x;
    const int d0 = c * 128;

    if (threadIdx.x < 128)
        qs[threadIdx.x] = query[b * D_ + d0 + threadIdx.x];
    __syncthreads();

    float acc = 0.0f;
#pragma unroll 8
    for (int i = 0; i < 128; ++i)
        acc = fmaf(qs[i], W2[(size_t)(d0 + i) * U_ + u], acc);
    g_qpart[(c * B_ + b) * U_ + u] = acc;
}

__global__ void qproj_reduce_kernel(const float* __restrict__ b1,
                                    const float* __restrict__ b2)
{
    const int i = blockIdx.x * 256 + threadIdx.x;   // over B*U
    const int u = i & (U_ - 1);
    float s = b1[u] + b2[u];
#pragma unroll
    for (int c = 0; c < 8; ++c)
        s += g_qpart[c * (B_ * U_) + i];
    g_cu[i] = s;
}

// ---------------------------------------------------------------------------
// Fused score GEMM (mma.sync fp16), 3-stage cp.async ring.
// Strength-reduced LDSM addressing (c-invariant swizzle terms kept in
// registers, +128 per c) and register double-buffered fragments (prefetch
// ks+1 under ks's mma burst).
// ---------------------------------------------------------------------------
#define NCHUNK 64                      // 4 passes x 16 chunks
#define SMA    0                       // 64 x 2048B = 131072
#define SMB    131072                  // 3 stages x 32768
#define SMRED  (SMB + 3 * 32768)       // 64 x 4 f32
#define SMTOT  (SMRED + 1024)          // 230400 bytes

__global__ void __launch_bounds__(256, 1)
score_kernel(const float* __restrict__ values,
             const float* __restrict__ V,
             const float* __restrict__ bv)
{
    extern __shared__ char smem[];
    const uint32_t sb = smem_u32(smem);
    const int tid  = threadIdx.x;
    const int lane = tid & 31;
    const int warp = tid >> 5;
    const int warp_m = warp & 1;
    const int warp_n = warp >> 1;
    const int g8 = lane >> 2;
    const int t4 = lane & 3;
    const int e  = lane >> 4;            // 0/1: which 8-col group of ldsm

    const int b  = blockIdx.x >> 5;          // 32 t-tiles per batch
    const int t0 = (blockIdx.x & 31) * 64;

    float* sred = (float*)(smem + SMRED);

    // chunk issue: 256u x 64k fp16 into stage gc%3
    auto issue_chunk = [&](int gc) {
        if (gc < NCHUNK) {
            const int p = gc >> 4, c = gc & 15;
            const __half* src0 = g_w1t + (size_t)(p * 256) * D_ + c * 64;
            uint32_t dbase = sb + SMB + (gc % 3) * 32768;
#pragma unroll
            for (int j = 0; j < 8; ++j) {
                int idx = tid + j * 256;       // 2048 slots of 16B
                int row = idx >> 3, cs = idx & 7;
                cp_async16(dbase + row * 128 + ((cs ^ (row & 7)) << 4),
                           src0 + (size_t)row * D_ + cs * 8);
            }
        }
        cp_commit();
    };

    // prologue FIRST: 2 chunks in flight while we load/convert A
    issue_chunk(0);
    issue_chunk(1);

    // ---- A resident: 64 rows x 1024 k, fp32 -> fp16, xor-swizzled ----
    const float* vbase = values + ((size_t)b * T_ + t0) * D_;
#pragma unroll 4
    for (int it = 0; it < 32; ++it) {
        int idx = tid + it * 256;             // 8192 slots of 8 fp16
        int row = idx >> 7;
        int c   = idx & 127;
        const float* src = vbase + (size_t)row * D_ + c * 8;
        float4 f0 = *(const float4*)(src);
        float4 f1 = *(const float4*)(src + 4);
        uint4 o;
        o.x = pack_f16x2(f0.x, f0.y);
        o.y = pack_f16x2(f0.z, f0.w);
        o.z = pack_f16x2(f1.x, f1.y);
        o.w = pack_f16x2(f1.z, f1.w);
        *(uint4*)(smem + SMA + row * 2048 + ((c ^ (row & 7)) << 4)) = o;
    }

    // ---- strength-reduced address bases ----
    // A: addr(mt,ks;c) = sb+SMA + rowA*2048 + (((2ks+e)^(rowA&7))<<4) + c*128
    uint32_t a_base[2][4];
#pragma unroll
    for (int mt = 0; mt < 2; ++mt) {
        int rowA = warp_m * 32 + mt * 16 + (lane & 15);
        int sA = rowA & 7;
#pragma unroll
        for (int ks = 0; ks < 4; ++ks)
            a_base[mt][ks] = sb + SMA + rowA * 2048 + (((2 * ks + e) ^ sA) << 4);
    }
    // B: addr(nt,ks;stage) = sb+SMB + rowB*128 + (((2ks+e)^(rowB&7))<<4) + stage*32768
    uint32_t b_rel[4][4];
#pragma unroll
    for (int nt = 0; nt < 4; ++nt) {
        int rowB = warp_n * 64 + nt * 16 + (lane & 15);
        int sB = rowB & 7;
#pragma unroll
        for (int ks = 0; ks < 4; ++ks)
            b_rel[nt][ks] = sb + SMB + rowB * 128 + (((2 * ks + e) ^ sB) << 4);
    }

    float spart[4] = {0.f, 0.f, 0.f, 0.f};
    int g = 0;

    for (int pass = 0; pass < 4; ++pass) {
        const int u0 = pass * 256;

        float acc[2][8][4];
#pragma unroll
        for (int mt = 0; mt < 2; ++mt)
#pragma unroll
            for (int j = 0; j < 8; ++j)
#pragma unroll
                for (int r = 0; r < 4; ++r) acc[mt][j][r] = 0.f;

        uint32_t a_adr[2][4];
#pragma unroll
        for (int mt = 0; mt < 2; ++mt)
#pragma unroll
            for (int ks = 0; ks < 4; ++ks) a_adr[mt][ks] = a_base[mt][ks];

        for (int c = 0; c < 16; ++c, ++g) {
            cp_wait1();
            __syncthreads();
            issue_chunk(g + 2);

            const uint32_t soff = (g % 3) * 32768;

            // register double-buffered fragments
            uint32_t af[2][2][4];     // [buf][mt][4]
            uint32_t bf[2][4][4];     // [buf][nt][4]
#pragma unroll
            for (int mt = 0; mt < 2; ++mt)
                ldsm_x4(af[0][mt][0], af[0][mt][1], af[0][mt][2], af[0][mt][3],
                        a_adr[mt][0]);
#pragma unroll
            for (int nt = 0; nt < 4; ++nt)
                ldsm_x4(bf[0][nt][0], bf[0][nt][1], bf[0][nt][2], bf[0][nt][3],
                        b_rel[nt][0] + soff);

#pragma unroll
            for (int ks = 0; ks < 4; ++ks) {
                const int cur = ks & 1, nxt = cur ^ 1;
                if (ks < 3) {
#pragma unroll
                    for (int mt = 0; mt < 2; ++mt)
                        ldsm_x4(af[nxt][mt][0], af[nxt][mt][1],
                                af[nxt][mt][2], af[nxt][mt][3],
                                a_adr[mt][ks + 1]);
#pragma unroll
                    for (int nt = 0; nt < 4; ++nt)
                        ldsm_x4(bf[nxt][nt][0], bf[nxt][nt][1],
                                bf[nxt][nt][2], bf[nxt][nt][3],
                                b_rel[nt][ks + 1] + soff);
                }
#pragma unroll
                for (int nt = 0; nt < 4; ++nt)
#pragma unroll
                    for (int mt = 0; mt < 2; ++mt) {
                        mma16816(acc[mt][nt * 2 + 0], af[cur][mt],
                                 bf[cur][nt][0], bf[cur][nt][2]);   // cols +0..7
                        mma16816(acc[mt][nt * 2 + 1], af[cur][mt],
                                 bf[cur][nt][1], bf[cur][nt][3]);   // cols +8..15
                    }
            }

            // advance A addresses for next c (k advances by 64 = 128 bytes)
#pragma unroll
            for (int mt = 0; mt < 2; ++mt)
#pragma unroll
                for (int ks = 0; ks < 4; ++ks) a_adr[mt][ks] += 128;
        }

        // ---- epilogue: tanh + dot V folded into per-row partials ----
        float cuv[16], vvv[16];
#pragma unroll
        for (int j = 0; j < 8; ++j)
#pragma unroll
            for (int ee = 0; ee < 2; ++ee) {
                int u = u0 + warp_n * 64 + j * 8 + t4 * 2 + ee;
                cuv[j * 2 + ee] = g_cu[b * U_ + u];
                vvv[j * 2 + ee] = V[u];
            }
#pragma unroll
        for (int mt = 0; mt < 2; ++mt)
#pragma unroll
            for (int j = 0; j < 8; ++j)
#pragma unroll
                for (int r = 0; r < 4; ++r) {
                    float x = acc[mt][j][r] + cuv[j * 2 + (r & 1)];
                    spart[mt * 2 + (r >> 1)] =
                        fmaf(tanhf(x), vvv[j * 2 + (r & 1)], spart[mt * 2 + (r >> 1)]);
                }
    }

    // reduce across quad lanes (cols), stash per-warp_n partials
#pragma unroll
    for (int s = 0; s < 4; ++s) {
        float v = spart[s];
        v += __shfl_xor_sync(0xffffffffu, v, 1);
        v += __shfl_xor_sync(0xffffffffu, v, 2);
        if (t4 == 0) {
            int row = warp_m * 32 + (s >> 1) * 16 + (s & 1) * 8 + g8;
            sred[row * 4 + warp_n] = v;
        }
    }
    __syncthreads();
    if (tid < 64) {
        const float* rp = &sred[tid * 4];
        g_logits[b * T_ + t0 + tid] = (rp[0] + rp[1]) + (rp[2] + rp[3]) + bv[0];
    }
}

// ---------------------------------------------------------------------------
// softmax over T per batch
// ---------------------------------------------------------------------------
__global__ void softmax_kernel(float* __restrict__ weights)
{
    __shared__ float red[256];
    const int b = blockIdx.x;
    const int tid = threadIdx.x;

    float m = -INFINITY;
    for (int t = tid; t < T_; t += 256)
        m = fmaxf(m, g_logits[b * T_ + t]);
    red[tid] = m;
    __syncthreads();
    for (int s = 128; s > 0; s >>= 1) {
        if (tid < s) red[tid] = fmaxf(red[tid], red[tid + s]);
        __syncthreads();
    }
    m = red[0];
    __syncthreads();

    float sum = 0.0f;
    for (int t = tid; t < T_; t += 256)
        sum += expf(g_logits[b * T_ + t] - m);
    red[tid] = sum;
    __syncthreads();
    for (int s = 128; s > 0; s >>= 1) {
        if (tid < s) red[tid] += red[tid + s];
        __syncthreads();
    }
    const float inv = 1.0f / red[0];

    for (int t = tid; t < T_; t += 256)
        weights[b * T_ + t] = expf(g_logits[b * T_ + t] - m) * inv;
}

// ---------------------------------------------------------------------------
// context: two-stage deterministic reduction over T, float4 loads
// ---------------------------------------------------------------------------
__global__ void context_part_kernel(const float* __restrict__ values,
                                    const float* __restrict__ weights)
{
    __shared__ float w[128];
    const int b = blockIdx.y;
    const int chunk = blockIdx.z;
    const int d4 = blockIdx.x * 64 + threadIdx.x;   // float4 index
    const int tbase = chunk * 128;

    for (int t = threadIdx.x; t < 128; t += 64)
        w[t] = weights[b * T_ + tbase + t];
    __syncthreads();

    const float4* vp4 = (const float4*)(values + ((size_t)b * T_ + tbase) * D_) + d4;
    float4 a0 = {0,0,0,0}, a1 = {0,0,0,0}, a2 = {0,0,0,0}, a3 = {0,0,0,0};
#pragma unroll 2
    for (int t = 0; t < 128; t += 4) {
        float4 f0 = vp4[(size_t)(t + 0) * (D_ / 4)];
        float4 f1 = vp4[(size_t)(t + 1) * (D_ / 4)];
        float4 f2 = vp4[(size_t)(t + 2) * (D_ / 4)];
        float4 f3 = vp4[(size_t)(t + 3) * (D_ / 4)];
        float w0 = w[t], w1 = w[t + 1], w2 = w[t + 2], w3 = w[t + 3];
        a0.x = fmaf(w0, f0.x, a0.x); a0.y = fmaf(w0, f0.y, a0.y);
        a0.z = fmaf(w0, f0.z, a0.z); a0.w = fmaf(w0, f0.w, a0.w);
        a1.x = fmaf(w1, f1.x, a1.x); a1.y = fmaf(w1, f1.y, a1.y);
        a1.z = fmaf(w1, f1.z, a1.z); a1.w = fmaf(w1, f1.w, a1.w);
        a2.x = fmaf(w2, f2.x, a2.x); a2.y = fmaf(w2, f2.y, a2.y);
        a2.z = fmaf(w2, f2.z, a2.z); a2.w = fmaf(w2, f2.w, a2.w);
        a3.x = fmaf(w3, f3.x, a3.x); a3.y = fmaf(w3, f3.y, a3.y);
        a3.z = fmaf(w3, f3.z, a3.z); a3.w = fmaf(w3, f3.w, a3.w);
    }
    float4 r;
    r.x = (a0.x + a1.x) + (a2.x + a3.x);
    r.y = (a0.y + a1.y) + (a2.y + a3.y);
    r.z = (a0.z + a1.z) + (a2.z + a3.z);
    r.w = (a0.w + a1.w) + (a2.w + a3.w);
    ((float4*)(g_cpart + (size_t)(chunk * B_ + b) * D_))[d4] = r;
}

__global__ void context_reduce_kernel(float* __restrict__ context)
{
    const int i = blockIdx.x * 256 + threadIdx.x;   // over B*D
    float s = 0.0f;
#pragma unroll
    for (int c = 0; c < 16; ++c)
        s += g_cpart[c * (B_ * D_) + i];
    context[i] = s;
}

// ---------------------------------------------------------------------------
extern "C" void kernel_launch(void* const* d_in, const int* in_sizes, int n_in,
                              void* d_out, int out_size)
{
    const float* query  = (const float*)d_in[0];
    const float* values = (const float*)d_in[1];
    const float* W1     = (const float*)d_in[2];
    const float* b1     = (const float*)d_in[3];
    const float* W2     = (const float*)d_in[4];
    const float* b2     = (const float*)d_in[5];
    const float* V      = (const float*)d_in[6];
    const float* bv     = (const float*)d_in[7];

    float* out     = (float*)d_out;
    float* context = out;             // [B, D]
    float* weights = out + B_ * D_;   // [B, T, 1]

    cudaFuncSetAttribute(score_kernel,
                         cudaFuncAttributeMaxDynamicSharedMemorySize, SMTOT);

    w1t_kernel<<<dim3(U_ / 32, D_ / 32), dim3(32, 8)>>>(W1);
    qproj_part_kernel<<<dim3(U_ / 256, B_, 8), 256>>>(query, W2);
    qproj_reduce_kernel<<<(B_ * U_) / 256, 256>>>(b1, b2);
    score_kernel<<<(B_ * T_) / 64, 256, SMTOT>>>(values, V, bv);
    softmax_kernel<<<B_, 256>>>(weights);
    context_part_kernel<<<dim3(D_ / 256, B_, 16), 64>>>(values, weights);
    context_reduce_kernel<<<(B_ * D_) / 256, 256>>>(context);
}